// round 1
// baseline (speedup 1.0000x reference)
#include <cuda_runtime.h>
#include <cstdint>

#define BB 64
#define TT 4000
#define FF 128

struct SampleParams {
    int valid_t;
    int ts0, te0, ts1, te1;
    unsigned fm[4];   // 128-bit freq mask
};

__device__ SampleParams g_params[BB];

// ---------------- Threefry-2x32, 20 rounds (JAX-compatible) ----------------
__device__ __forceinline__ void tf2x32(unsigned k0, unsigned k1,
                                       unsigned x0, unsigned x1,
                                       unsigned &o0, unsigned &o1) {
    unsigned ks2 = k0 ^ k1 ^ 0x1BD11BDAu;
    x0 += k0; x1 += k1;
#define TF_R(r) { x0 += x1; x1 = (x1 << (r)) | (x1 >> (32 - (r))); x1 ^= x0; }
    TF_R(13) TF_R(15) TF_R(26) TF_R(6)
    x0 += k1;  x1 += ks2 + 1u;
    TF_R(17) TF_R(29) TF_R(16) TF_R(24)
    x0 += ks2; x1 += k0 + 2u;
    TF_R(13) TF_R(15) TF_R(26) TF_R(6)
    x0 += k0;  x1 += k1 + 3u;
    TF_R(17) TF_R(29) TF_R(16) TF_R(24)
    x0 += k1;  x1 += ks2 + 4u;
    TF_R(13) TF_R(15) TF_R(26) TF_R(6)
    x0 += ks2; x1 += k0 + 5u;
#undef TF_R
    o0 = x0; o1 = x1;
}

// partitionable (counter-mode) random bits at flat index i (< 2^32)
__device__ __forceinline__ unsigned rb32(unsigned k0, unsigned k1, unsigned i) {
    unsigned a, b; tf2x32(k0, k1, 0u, i, a, b);
    return a ^ b;
}
__device__ __forceinline__ unsigned long long rb64(unsigned k0, unsigned k1, unsigned i) {
    unsigned a, b; tf2x32(k0, k1, 0u, i, a, b);
    return ((unsigned long long)a << 32) | (unsigned long long)b;
}
__device__ __forceinline__ float u32_to_f(unsigned bits) {
    return __uint_as_float((bits >> 9) | 0x3F800000u) - 1.0f;
}
__device__ __forceinline__ double u64_to_d(unsigned long long bits) {
    return __longlong_as_double((long long)((bits >> 12) | 0x3FF0000000000000ULL)) - 1.0;
}

// ---------------- Setup: compute per-sample mask params -------------------
__global__ void setup_kernel(const void* __restrict__ lengths_raw) {
    __shared__ int s_is64;
    int b = threadIdx.x;
    if (b == 0) {
        // lengths values are in [0, 4000). If stored as int64, every 8-byte
        // word is in range. If stored as int32, 8-byte reads combine pairs
        // and the high word is almost surely nonzero somewhere.
        const long long* p = (const long long*)lengths_raw;
        int ok = 1;
        for (int i = 0; i < 32; i++) {
            long long v = p[i];
            if (v < 0 || v >= 4096) { ok = 0; break; }
        }
        s_is64 = ok;
    }
    __syncthreads();
    if (b >= BB) return;
    const int is64 = s_is64;

    int valid_t = is64 ? (int)((const long long*)lengths_raw)[b]
                       : ((const int*)lengths_raw)[b];

    // key(42) -> split into 4 derived keys (fold-like: counts (0, i))
    unsigned kfw0,kfw1, kfs0,kfs1, ktw0,ktw1, kts0,kts1;
    tf2x32(0u, 42u, 0u, 0u, kfw0, kfw1);
    tf2x32(0u, 42u, 0u, 1u, kfs0, kfs1);
    tf2x32(0u, 42u, 0u, 2u, ktw0, ktw1);
    tf2x32(0u, 42u, 0u, 3u, kts0, kts1);
    // randint internally splits kf_w into two streams
    unsigned ka0,ka1, kb0,kb1;
    tf2x32(kfw0, kfw1, 0u, 0u, ka0, ka1);
    tf2x32(kfw0, kfw1, 0u, 1u, kb0, kb1);

    // ---- frequency masks ----
    unsigned fm[4] = {0u,0u,0u,0u};
    #pragma unroll
    for (int j = 0; j < 2; j++) {
        unsigned i = (unsigned)(b * 2 + j);
        int w, fs;
        if (!is64) {
            // 32-bit randint, span=31: mult = (2^16 % 31)^2 % 31 = 4
            unsigned hb = rb32(ka0, ka1, i);
            unsigned lb = rb32(kb0, kb1, i);
            unsigned off = ((hb % 31u) * 4u + (lb % 31u)) % 31u;
            w = (int)off;
            float fu = u32_to_f(rb32(kfs0, kfs1, i));
            fs = (int)floorf(fu * (float)(FF - w + 1));
        } else {
            // 64-bit randint, span=31: mult = (2^32 % 31)^2 % 31 = 16
            unsigned long long hb = rb64(ka0, ka1, i);
            unsigned long long lb = rb64(kb0, kb1, i);
            unsigned long long off = ((hb % 31ULL) * 16ULL + (lb % 31ULL)) % 31ULL;
            w = (int)off;
            double fu = u64_to_d(rb64(kfs0, kfs1, i));
            fs = (int)floor(fu * (double)(float)(FF - w + 1));
        }
        if (w > 0 && w < FF) {
            int lo = fs, hi = fs + w;
            #pragma unroll
            for (int k = 0; k < 4; k++) {
                int a = lo - 32 * k; if (a < 0) a = 0;
                int e = hi - 32 * k; if (e > 32) e = 32;
                if (a < e) {
                    unsigned m = (e == 32) ? 0xFFFFFFFFu : ((1u << e) - 1u);
                    if (a > 0) m &= ~((1u << a) - 1u);
                    fm[k] |= m;
                }
            }
        }
    }

    // ---- time masks ----
    int twmax = valid_t < 40 ? valid_t : 40;
    int ts[2], te[2];
    #pragma unroll
    for (int j = 0; j < 2; j++) {
        unsigned i = (unsigned)(b * 2 + j);
        int tw, tstart;
        if (!is64) {
            float tu = u32_to_f(rb32(ktw0, ktw1, i));
            tw = (int)floorf(tu * (float)(twmax + 1));
            if (tw > twmax) tw = twmax;
            int sr = valid_t - tw + 1; if (sr < 1) sr = 1;
            float su = u32_to_f(rb32(kts0, kts1, i));
            tstart = (int)floorf(su * (float)sr);
        } else {
            double tu = u64_to_d(rb64(ktw0, ktw1, i));
            tw = (int)floor(tu * (double)(float)(twmax + 1));
            if (tw > twmax) tw = twmax;
            int sr = valid_t - tw + 1; if (sr < 1) sr = 1;
            double su = u64_to_d(rb64(kts0, kts1, i));
            tstart = (int)floor(su * (double)(float)sr);
        }
        bool tvalid = (tw > 0) && (tw < valid_t) && (valid_t > 0);
        if (tvalid) { ts[j] = tstart; te[j] = tstart + tw; }
        else        { ts[j] = 0;      te[j] = 0; }
    }

    SampleParams sp;
    sp.valid_t = valid_t;
    sp.ts0 = ts[0]; sp.te0 = te[0];
    sp.ts1 = ts[1]; sp.te1 = te[1];
    sp.fm[0] = fm[0]; sp.fm[1] = fm[1]; sp.fm[2] = fm[2]; sp.fm[3] = fm[3];
    g_params[b] = sp;
}

// ---------------- Main: streaming masked copy ------------------------------
__global__ void __launch_bounds__(256)
mask_kernel(const float4* __restrict__ src, float4* __restrict__ dst) {
    int b    = blockIdx.y;
    int warp = threadIdx.x >> 5;
    int lane = threadIdx.x & 31;
    int t    = blockIdx.x * 8 + warp;            // 500 blocks * 8 warps = 4000 rows

    const SampleParams* p = &g_params[b];
    int vt  = p->valid_t;
    int ts0 = p->ts0, te0 = p->te0, ts1 = p->ts1, te1 = p->te1;

    size_t idx = ((size_t)b * TT + t) * (FF / 4) + lane;
    float4 v = src[idx];

    bool tm = (t >= ts0 && t < te0) || (t >= ts1 && t < te1);
    if (tm) {
        v.x = 0.0f; v.y = 0.0f; v.z = 0.0f; v.w = 0.0f;
    } else if (t < vt) {
        unsigned word = p->fm[lane >> 3];
        unsigned bits = (word >> ((lane & 7) << 2)) & 0xFu;
        if (bits & 1u) v.x = 0.0f;
        if (bits & 2u) v.y = 0.0f;
        if (bits & 4u) v.z = 0.0f;
        if (bits & 8u) v.w = 0.0f;
    }
    dst[idx] = v;
}

extern "C" void kernel_launch(void* const* d_in, const int* in_sizes, int n_in,
                              void* d_out, int out_size) {
    // identify inputs (mel is the huge one)
    const void* mel = d_in[0];
    const void* len = d_in[1];
    if (n_in >= 2 && in_sizes[0] == BB && in_sizes[1] != BB) {
        mel = d_in[1]; len = d_in[0];
    }

    setup_kernel<<<1, 64>>>(len);

    dim3 grid(TT / 8, BB);
    mask_kernel<<<grid, 256>>>((const float4*)mel, (float4*)d_out);
}

// round 2
// speedup vs baseline: 1.0901x; 1.0901x over previous
#include <cuda_runtime.h>
#include <cstdint>

#define BB 64
#define TT 4000
#define FF 128
#define ROWS_PER_BLOCK 32   // 8 warps * 4 rows each

// ================= compile-time Threefry-2x32 (20 rounds) =================
struct TF2 { unsigned a, b; };

__host__ __device__ constexpr unsigned rotl_c(unsigned x, int r) {
    return (x << r) | (x >> (32 - r));
}

__host__ __device__ constexpr TF2 tf2_c(unsigned k0, unsigned k1,
                                        unsigned x0, unsigned x1) {
    unsigned ks2 = k0 ^ k1 ^ 0x1BD11BDAu;
    x0 += k0; x1 += k1;
    // group 1
    x0 += x1; x1 = rotl_c(x1, 13) ^ x0;
    x0 += x1; x1 = rotl_c(x1, 15) ^ x0;
    x0 += x1; x1 = rotl_c(x1, 26) ^ x0;
    x0 += x1; x1 = rotl_c(x1,  6) ^ x0;
    x0 += k1;  x1 += ks2 + 1u;
    // group 2
    x0 += x1; x1 = rotl_c(x1, 17) ^ x0;
    x0 += x1; x1 = rotl_c(x1, 29) ^ x0;
    x0 += x1; x1 = rotl_c(x1, 16) ^ x0;
    x0 += x1; x1 = rotl_c(x1, 24) ^ x0;
    x0 += ks2; x1 += k0 + 2u;
    // group 3
    x0 += x1; x1 = rotl_c(x1, 13) ^ x0;
    x0 += x1; x1 = rotl_c(x1, 15) ^ x0;
    x0 += x1; x1 = rotl_c(x1, 26) ^ x0;
    x0 += x1; x1 = rotl_c(x1,  6) ^ x0;
    x0 += k0;  x1 += k1 + 3u;
    // group 4
    x0 += x1; x1 = rotl_c(x1, 17) ^ x0;
    x0 += x1; x1 = rotl_c(x1, 29) ^ x0;
    x0 += x1; x1 = rotl_c(x1, 16) ^ x0;
    x0 += x1; x1 = rotl_c(x1, 24) ^ x0;
    x0 += k1;  x1 += ks2 + 4u;
    // group 5
    x0 += x1; x1 = rotl_c(x1, 13) ^ x0;
    x0 += x1; x1 = rotl_c(x1, 15) ^ x0;
    x0 += x1; x1 = rotl_c(x1, 26) ^ x0;
    x0 += x1; x1 = rotl_c(x1,  6) ^ x0;
    x0 += ks2; x1 += k0 + 5u;
    return TF2{x0, x1};
}

// key(42) -> split 4 derived keys (counter-mode counts (0, i))
constexpr TF2 KFW = tf2_c(0u, 42u, 0u, 0u);
constexpr TF2 KFS = tf2_c(0u, 42u, 0u, 1u);
constexpr TF2 KTW = tf2_c(0u, 42u, 0u, 2u);
constexpr TF2 KTS = tf2_c(0u, 42u, 0u, 3u);
// randint internally splits kf_w into two streams
constexpr TF2 KA  = tf2_c(KFW.a, KFW.b, 0u, 0u);
constexpr TF2 KB  = tf2_c(KFW.a, KFW.b, 0u, 1u);

// ====================== runtime Threefry (leaf draws) ======================
__device__ __forceinline__ void tf2x32(unsigned k0, unsigned k1,
                                       unsigned x0, unsigned x1,
                                       unsigned &o0, unsigned &o1) {
    unsigned ks2 = k0 ^ k1 ^ 0x1BD11BDAu;
    x0 += k0; x1 += k1;
#define TF_R(r) { x0 += x1; x1 = (x1 << (r)) | (x1 >> (32 - (r))); x1 ^= x0; }
    TF_R(13) TF_R(15) TF_R(26) TF_R(6)
    x0 += k1;  x1 += ks2 + 1u;
    TF_R(17) TF_R(29) TF_R(16) TF_R(24)
    x0 += ks2; x1 += k0 + 2u;
    TF_R(13) TF_R(15) TF_R(26) TF_R(6)
    x0 += k0;  x1 += k1 + 3u;
    TF_R(17) TF_R(29) TF_R(16) TF_R(24)
    x0 += k1;  x1 += ks2 + 4u;
    TF_R(13) TF_R(15) TF_R(26) TF_R(6)
    x0 += ks2; x1 += k0 + 5u;
#undef TF_R
    o0 = x0; o1 = x1;
}

__device__ __forceinline__ unsigned rb32(unsigned k0, unsigned k1, unsigned i) {
    unsigned a, b; tf2x32(k0, k1, 0u, i, a, b);
    return a ^ b;
}
__device__ __forceinline__ unsigned long long rb64(unsigned k0, unsigned k1, unsigned i) {
    unsigned a, b; tf2x32(k0, k1, 0u, i, a, b);
    return ((unsigned long long)a << 32) | (unsigned long long)b;
}
__device__ __forceinline__ float u32_to_f(unsigned bits) {
    return __uint_as_float((bits >> 9) | 0x3F800000u) - 1.0f;
}
__device__ __forceinline__ double u64_to_d(unsigned long long bits) {
    return __longlong_as_double((long long)((bits >> 12) | 0x3FF0000000000000ULL)) - 1.0;
}

// ============================ fused kernel =================================
__global__ void __launch_bounds__(256)
fused_kernel(const float4* __restrict__ src, float4* __restrict__ dst,
             const void* __restrict__ len_raw) {
    __shared__ int      s_vt;
    __shared__ int      s_ts[2], s_te[2];
    __shared__ unsigned s_fm[4];

    const int b    = blockIdx.y;
    const int tid  = threadIdx.x;
    const int warp = tid >> 5;
    const int lane = tid & 31;
    const int t0   = blockIdx.x * ROWS_PER_BLOCK + warp * 4;

    // ---- issue the block's loads first (4 independent LDG.128 per thread) ----
    const size_t base = ((size_t)b * TT + t0) * (FF / 4) + lane;
    float4 v0 = src[base];
    float4 v1 = src[base + 32];
    float4 v2 = src[base + 64];
    float4 v3 = src[base + 96];

    // ---- param compute (thread 0) overlapped with the loads in flight ----
    if (tid == 0) {
        // dtype auto-detect: int64 lengths are all < 4096 when read as u64;
        // int32 pairs combine to huge values unless every odd length == 0.
        const unsigned long long* lp = (const unsigned long long*)len_raw;
        unsigned long long m = 0;
        #pragma unroll
        for (int i = 0; i < 16; i++) m |= lp[i];
        const int is64 = (m < 4096ULL);

        const int vt = is64 ? (int)((const long long*)len_raw)[b]
                            : ((const int*)len_raw)[b];
        s_vt = vt;

        unsigned fm[4] = {0u, 0u, 0u, 0u};
        const int twmax = vt < 40 ? vt : 40;

        #pragma unroll
        for (int j = 0; j < 2; j++) {
            const unsigned i = (unsigned)(b * 2 + j);
            int w, fs, tw, tstart;
            if (!is64) {
                unsigned hb = rb32(KA.a, KA.b, i);
                unsigned lb = rb32(KB.a, KB.b, i);
                w  = (int)(((hb % 31u) * 4u + (lb % 31u)) % 31u);
                float fu = u32_to_f(rb32(KFS.a, KFS.b, i));
                fs = (int)floorf(fu * (float)(FF - w + 1));
                float tu = u32_to_f(rb32(KTW.a, KTW.b, i));
                tw = (int)floorf(tu * (float)(twmax + 1));
                if (tw > twmax) tw = twmax;
                int sr = vt - tw + 1; if (sr < 1) sr = 1;
                float su = u32_to_f(rb32(KTS.a, KTS.b, i));
                tstart = (int)floorf(su * (float)sr);
            } else {
                unsigned long long hb = rb64(KA.a, KA.b, i);
                unsigned long long lb = rb64(KB.a, KB.b, i);
                w  = (int)(((hb % 31ULL) * 16ULL + (lb % 31ULL)) % 31ULL);
                double fu = u64_to_d(rb64(KFS.a, KFS.b, i));
                fs = (int)floor(fu * (double)(float)(FF - w + 1));
                double tu = u64_to_d(rb64(KTW.a, KTW.b, i));
                tw = (int)floor(tu * (double)(float)(twmax + 1));
                if (tw > twmax) tw = twmax;
                int sr = vt - tw + 1; if (sr < 1) sr = 1;
                double su = u64_to_d(rb64(KTS.a, KTS.b, i));
                tstart = (int)floor(su * (double)(float)sr);
            }

            // freq interval -> 128-bit mask
            if (w > 0 && w < FF) {
                const int lo = fs, hi = fs + w;
                #pragma unroll
                for (int k = 0; k < 4; k++) {
                    int a = lo - 32 * k; if (a < 0) a = 0;
                    int e = hi - 32 * k; if (e > 32) e = 32;
                    if (a < e) {
                        unsigned mm = (e == 32) ? 0xFFFFFFFFu : ((1u << e) - 1u);
                        if (a > 0) mm &= ~((1u << a) - 1u);
                        fm[k] |= mm;
                    }
                }
            }

            // time interval
            const bool tvalid = (tw > 0) && (tw < vt) && (vt > 0);
            s_ts[j] = tvalid ? tstart : 0;
            s_te[j] = tvalid ? tstart + tw : 0;
        }
        s_fm[0] = fm[0]; s_fm[1] = fm[1]; s_fm[2] = fm[2]; s_fm[3] = fm[3];
    }
    __syncthreads();

    const int vt  = s_vt;
    const int ts0 = s_ts[0], te0 = s_te[0], ts1 = s_ts[1], te1 = s_te[1];
    const unsigned word = s_fm[lane >> 3];
    const unsigned nib  = (word >> ((lane & 7) << 2)) & 0xFu;

    #pragma unroll
    for (int k = 0; k < 4; k++) {
        float4& v = (k == 0) ? v0 : (k == 1) ? v1 : (k == 2) ? v2 : v3;
        const int t = t0 + k;
        const bool tm = (t >= ts0 && t < te0) || (t >= ts1 && t < te1);
        if (tm) {
            v.x = 0.0f; v.y = 0.0f; v.z = 0.0f; v.w = 0.0f;
        } else if (t < vt) {
            if (nib & 1u) v.x = 0.0f;
            if (nib & 2u) v.y = 0.0f;
            if (nib & 4u) v.z = 0.0f;
            if (nib & 8u) v.w = 0.0f;
        }
        dst[base + 32 * k] = v;
    }
}

extern "C" void kernel_launch(void* const* d_in, const int* in_sizes, int n_in,
                              void* d_out, int out_size) {
    const void* mel = d_in[0];
    const void* len = d_in[1];
    if (n_in >= 2 && in_sizes[0] == BB && in_sizes[1] != BB) {
        mel = d_in[1]; len = d_in[0];
    }

    dim3 grid(TT / ROWS_PER_BLOCK, BB);   // (125, 64)
    fused_kernel<<<grid, 256>>>((const float4*)mel, (float4*)d_out, len);
}